// round 14
// baseline (speedup 1.0000x reference)
#include <cuda_runtime.h>
#include <math.h>

#define NTAPS 201
#define HALF  100
#define NT3   204           // taps 0..202 used + zero row 203; 204 = 2*102
#define TILE  128           // threads; each thread computes 2 adjacent outputs
#define OUTS  256           // outputs per block
#define WIN   464           // window entries (need 461)
#define STP   233           // per-array stride (ulonglong2 units), odd to de-conflict
#define DYNBYTES (10 * STP * 16)
#define NW    (NT3 * 10)    // weight table: 10 ull per tap

typedef unsigned long long ull;

// Weight table in CONSTANT memory: warp-uniform accesses compile to LDCU into
// uniform registers, so the accumulate FFMA2s carry only 2 distinct vector-RF
// 64-bit operands (acc, product) -> RF-bank rt stays 2 (1.5x over 3-vec-operand).
__constant__ ull cW[NW];
__device__ ull gWstage[NW];

__device__ __forceinline__ ull pk(float lo, float hi) {
    ull r; asm("mov.b64 %0, {%1, %2};" : "=l"(r) : "f"(lo), "f"(hi)); return r;
}
__device__ __forceinline__ float2 upk(ull v) {
    float2 r; asm("mov.b64 {%0, %1}, %2;" : "=f"(r.x), "=f"(r.y) : "l"(v)); return r;
}
__device__ __forceinline__ void fma2(ull &d, ull a, ull b) {
    asm("fma.rn.f32x2 %0, %1, %2, %0;" : "+l"(d) : "l"(a), "l"(b));
}

// Per tap j, 10 ull rows in cW:
//   [10j+0,1] = w(+1) splats {(wr,wr),(wi,wi)}   [10j+2,3] = w(+2)
//   [10j+4,5] = w(-1) (tap-shifted)              [10j+6,7] = w(-2)
//   [10j+8]   = (wx,wx) ixpm                     [10j+9]   = (wq,wq) icixpm
__global__ void prep_weights(const float* __restrict__ ixpm_w,
                             const float* __restrict__ icixpm_w,
                             const float* __restrict__ fwm_wr,
                             const float* __restrict__ fwm_wi)
{
    int j = blockIdx.x * blockDim.x + threadIdx.x;
    if (j >= NT3) return;
    float wrP1 = (j <= 200) ? fwm_wr[2 * NTAPS + j] : 0.f;
    float wiP1 = (j <= 200) ? fwm_wi[2 * NTAPS + j] : 0.f;
    float wrP2 = (j <= 200) ? fwm_wr[3 * NTAPS + j] : 0.f;
    float wiP2 = (j <= 200) ? fwm_wi[3 * NTAPS + j] : 0.f;
    float wrM1 = (j >= 1 && j <= 201) ? fwm_wr[1 * NTAPS + (j - 1)] : 0.f;
    float wiM1 = (j >= 1 && j <= 201) ? fwm_wi[1 * NTAPS + (j - 1)] : 0.f;
    float wrM2 = (j >= 2 && j <= 202) ? fwm_wr[0 * NTAPS + (j - 2)] : 0.f;
    float wiM2 = (j >= 2 && j <= 202) ? fwm_wi[0 * NTAPS + (j - 2)] : 0.f;
    float wx   = (j <= 200) ? ixpm_w[j]   : 0.f;
    float wq   = (j <= 200) ? icixpm_w[j] : 0.f;
    gWstage[10 * j + 0] = pk(wrP1, wrP1);
    gWstage[10 * j + 1] = pk(wiP1, wiP1);
    gWstage[10 * j + 2] = pk(wrP2, wrP2);
    gWstage[10 * j + 3] = pk(wiP2, wiP2);
    gWstage[10 * j + 4] = pk(wrM1, wrM1);
    gWstage[10 * j + 5] = pk(wiM1, wiM1);
    gWstage[10 * j + 6] = pk(wrM2, wrM2);
    gWstage[10 * j + 7] = pk(wiM2, wiM2);
    gWstage[10 * j + 8] = pk(wx, wx);
    gWstage[10 * j + 9] = pk(wq, wq);
}

// accumulate one tap: products E0..E4, current weights W* (output A),
// previous-tap weights P* (output B). Weight args are plain ulls (UR-eligible).
#define ACC_TAP(E0,E1,E2,E3,E4, WA0,WA1,WB0,WB1,WC0,WC1,WD0,WD1,WE0,WE1,      \
                PA0,PA1,PB0,PB1,PC0,PC1,PD0,PD1,PE0,PE1) do {                 \
    ull d0=(E0).x, d1=(E0).y, d2=(E1).x, d3=(E1).y;                           \
    ull d4=(E2).x, d5=(E2).y, d6=(E3).x, d7=(E3).y;                           \
    ull qd=(E4).x, ps=(E4).y;                                                 \
    fma2(axpA, ps, (WE0));  fma2(axpB, ps, (PE0));                            \
    fma2(qcA,  qd, (WE1));  fma2(qcB,  qd, (PE1));                            \
    fma2(ApA[0], d0, (WA0)); fma2(BpA[0], d0, (WA1));                         \
    fma2(AmA[0], d0, (WC0)); fma2(BmA[0], d0, (WC1));                         \
    fma2(ApB[0], d0, (PA0)); fma2(BpB[0], d0, (PA1));                         \
    fma2(AmB[0], d0, (PC0)); fma2(BmB[0], d0, (PC1));                         \
    fma2(ApA[1], d1, (WA0)); fma2(BpA[1], d1, (WA1));                         \
    fma2(AmA[1], d1, (WC0)); fma2(BmA[1], d1, (WC1));                         \
    fma2(ApB[1], d1, (PA0)); fma2(BpB[1], d1, (PA1));                         \
    fma2(AmB[1], d1, (PC0)); fma2(BmB[1], d1, (PC1));                         \
    fma2(ApA[2], d2, (WA0)); fma2(BpA[2], d2, (WA1));                         \
    fma2(AmA[2], d2, (WC0)); fma2(BmA[2], d2, (WC1));                         \
    fma2(ApB[2], d2, (PA0)); fma2(BpB[2], d2, (PA1));                         \
    fma2(AmB[2], d2, (PC0)); fma2(BmB[2], d2, (PC1));                         \
    fma2(ApA[3], d3, (WA0)); fma2(BpA[3], d3, (WA1));                         \
    fma2(AmA[3], d3, (WC0)); fma2(BmA[3], d3, (WC1));                         \
    fma2(ApB[3], d3, (PA0)); fma2(BpB[3], d3, (PA1));                         \
    fma2(AmB[3], d3, (PC0)); fma2(BmB[3], d3, (PC1));                         \
    fma2(ApA[4], d4, (WB0)); fma2(BpA[4], d4, (WB1));                         \
    fma2(AmA[4], d4, (WD0)); fma2(BmA[4], d4, (WD1));                         \
    fma2(ApB[4], d4, (PB0)); fma2(BpB[4], d4, (PB1));                         \
    fma2(AmB[4], d4, (PD0)); fma2(BmB[4], d4, (PD1));                         \
    fma2(ApA[5], d5, (WB0)); fma2(BpA[5], d5, (WB1));                         \
    fma2(AmA[5], d5, (WD0)); fma2(BmA[5], d5, (WD1));                         \
    fma2(ApB[5], d5, (PB0)); fma2(BpB[5], d5, (PB1));                         \
    fma2(AmB[5], d5, (PD0)); fma2(BmB[5], d5, (PD1));                         \
    fma2(ApA[6], d6, (WB0)); fma2(BpA[6], d6, (WB1));                         \
    fma2(AmA[6], d6, (WD0)); fma2(BmA[6], d6, (WD1));                         \
    fma2(ApB[6], d6, (PB0)); fma2(BpB[6], d6, (PB1));                         \
    fma2(AmB[6], d6, (PD0)); fma2(BmB[6], d6, (PD1));                         \
    fma2(ApA[7], d7, (WB0)); fma2(BpA[7], d7, (WB1));                         \
    fma2(AmA[7], d7, (WD0)); fma2(BmA[7], d7, (WD1));                         \
    fma2(ApB[7], d7, (PB0)); fma2(BpB[7], d7, (PB1));                         \
    fma2(AmB[7], d7, (PD0)); fma2(BmB[7], d7, (PD1));                         \
} while (0)

__global__ __launch_bounds__(TILE, 3)
void snse_kernel(const float* __restrict__ x_real,
                 const float* __restrict__ x_imag,
                 const float* __restrict__ task_info,
                 const float* __restrict__ C00p,
                 const float* __restrict__ ixpm_w,
                 const float* __restrict__ icixpm_w,
                 float* __restrict__ out,
                 int M, int Lout)
{
    __shared__ ulonglong2 sU[WIN];
    extern __shared__ ulonglong2 sD[];     // 10 arrays of STP ulonglong2

    const int b  = blockIdx.y;
    const int l0 = blockIdx.x * OUTS;
    const int t  = threadIdx.x;

    const float dbm = task_info[b * 4];
    const float P   = exp10f(dbm * 0.1f) * 0.5f;   // /Nm, Nm=2
    const float sP  = sqrtf(P);
    const float rsP = 1.0f / sP;
    const float C00 = C00p[0];

    // ---- load scaled x window with mod-M wrap ----
    const float* xr = x_real + (size_t)b * M * 2;
    const float* xi = x_imag + (size_t)b * M * 2;
    for (int idx = t; idx < WIN; idx += TILE) {
        int g  = l0 - 2 + idx;
        int gm = (g < 0) ? g + M : ((g >= M) ? g - M : g);
        float r0 = xr[gm * 2 + 0] * sP, r1 = xr[gm * 2 + 1] * sP;
        float i0 = xi[gm * 2 + 0] * sP, i1 = xi[gm * 2 + 1] * sP;
        sU[idx] = make_ulonglong2(pk(r0, i0), pk(r1, i1));
    }
    __syncthreads();

    // ---- phase 1: per-position products into parity-split arrays ----
    // arrays 0..4 even p / 5..9 odd p, index p>>1
    for (int idx = t; idx < 459; idx += TILE) {
        int p = idx + 2;
        ulonglong2 u0 = sU[p], u1 = sU[p - 1], u2 = sU[p - 2];
        float2 f0 = upk(u0.x), f1 = upk(u0.y);
        float2 a0 = upk(u1.x), a1 = upk(u1.y);
        float2 b0 = upk(u2.x), b1 = upk(u2.y);
        int po = (p & 1) * 5;
        int ix = p >> 1;
        sD[(po + 0) * STP + ix] = make_ulonglong2(
            pk(f0.x * a0.x + f0.y * a0.y, f0.y * a0.x - f0.x * a0.y),
            pk(f0.x * a1.x + f0.y * a1.y, f0.y * a1.x - f0.x * a1.y));
        sD[(po + 1) * STP + ix] = make_ulonglong2(
            pk(f1.x * a0.x + f1.y * a0.y, f1.y * a0.x - f1.x * a0.y),
            pk(f1.x * a1.x + f1.y * a1.y, f1.y * a1.x - f1.x * a1.y));
        sD[(po + 2) * STP + ix] = make_ulonglong2(
            pk(f0.x * b0.x + f0.y * b0.y, f0.y * b0.x - f0.x * b0.y),
            pk(f0.x * b1.x + f0.y * b1.y, f0.y * b1.x - f0.x * b1.y));
        sD[(po + 3) * STP + ix] = make_ulonglong2(
            pk(f1.x * b0.x + f1.y * b0.y, f1.y * b0.x - f1.x * b0.y),
            pk(f1.x * b1.x + f1.y * b1.y, f1.y * b1.x - f1.x * b1.y));
        float p0 = f0.x * f0.x + f0.y * f0.y;
        float p1 = f1.x * f1.x + f1.y * f1.y;
        sD[(po + 4) * STP + ix] = make_ulonglong2(
            pk(f0.x * f1.x + f0.y * f1.y, f0.y * f1.x - f0.x * f1.y),
            pk(2.f * p0 + p1, 2.f * p1 + p0));
    }
    __syncthreads();

    const int base = 2 * t;
    const int lA = l0 + base;

    // ---- accumulators for BOTH outputs ----
    ull ApA[8], BpA[8], AmA[8], BmA[8];
    ull ApB[8], BpB[8], AmB[8], BmB[8];
#pragma unroll
    for (int k = 0; k < 8; ++k) {
        ApA[k] = BpA[k] = AmA[k] = BmA[k] = 0ULL;
        ApB[k] = BpB[k] = AmB[k] = BmB[k] = 0ULL;
    }
    ull axpA = 0ULL, axpB = 0ULL;
    ull qcA  = 0ULL, qcB  = 0ULL;

    // previous-tap weights (for output B); zero before tap 0
    ull pA0 = 0, pA1 = 0, pB0 = 0, pB1 = 0, pC0 = 0, pC1 = 0;
    ull pD0 = 0, pD1 = 0, pE0 = 0, pE1 = 0;

    // taps in parity pairs; products at consecutive lane indices (coalesced)
#pragma unroll 2
    for (int k = 0; k < NT3 / 2; ++k) {
        const int ix = t + 1 + k;
        // even tap j = 2k : weights cW[20k + 0..9]
        ulonglong2 e0 = sD[0 * STP + ix];
        ulonglong2 e1 = sD[1 * STP + ix];
        ulonglong2 e2 = sD[2 * STP + ix];
        ulonglong2 e3 = sD[3 * STP + ix];
        ulonglong2 e4 = sD[4 * STP + ix];
        ull wA0 = cW[20 * k + 0], wA1 = cW[20 * k + 1];
        ull wB0 = cW[20 * k + 2], wB1 = cW[20 * k + 3];
        ull wC0 = cW[20 * k + 4], wC1 = cW[20 * k + 5];
        ull wD0 = cW[20 * k + 6], wD1 = cW[20 * k + 7];
        ull wE0 = cW[20 * k + 8], wE1 = cW[20 * k + 9];
        ACC_TAP(e0, e1, e2, e3, e4,
                wA0, wA1, wB0, wB1, wC0, wC1, wD0, wD1, wE0, wE1,
                pA0, pA1, pB0, pB1, pC0, pC1, pD0, pD1, pE0, pE1);

        // odd tap j = 2k+1 : weights cW[20k + 10..19]; B side uses even tap's
        ulonglong2 o0 = sD[5 * STP + ix];
        ulonglong2 o1 = sD[6 * STP + ix];
        ulonglong2 o2 = sD[7 * STP + ix];
        ulonglong2 o3 = sD[8 * STP + ix];
        ulonglong2 o4 = sD[9 * STP + ix];
        ull vA0 = cW[20 * k + 10], vA1 = cW[20 * k + 11];
        ull vB0 = cW[20 * k + 12], vB1 = cW[20 * k + 13];
        ull vC0 = cW[20 * k + 14], vC1 = cW[20 * k + 15];
        ull vD0 = cW[20 * k + 16], vD1 = cW[20 * k + 17];
        ull vE0 = cW[20 * k + 18], vE1 = cW[20 * k + 19];
        ACC_TAP(o0, o1, o2, o3, o4,
                vA0, vA1, vB0, vB1, vC0, vC1, vD0, vD1, vE0, vE1,
                wA0, wA1, wB0, wB1, wC0, wC1, wD0, wD1, wE0, wE1);

        pA0 = vA0; pA1 = vA1; pB0 = vB0; pB1 = vB1; pC0 = vC0; pC1 = vC1;
        pD0 = vD0; pD1 = vD1; pE0 = vE0; pE1 = vE1;
    }

    const float wxc = ixpm_w[HALF];
    const float wqc = icixpm_w[HALF];

#pragma unroll
    for (int o = 0; o < 2; ++o) {
        const int l = lA + o;
        if (l >= Lout) break;
        const int bi = base + o;
        const ull* Ap = o ? ApB : ApA;
        const ull* Bp = o ? BpB : BpA;
        const ull* Am = o ? AmB : AmA;
        const ull* Bm = o ? BmB : BmA;
        float2 axpf = upk(o ? axpB : axpA);
        float2 qcf  = upk(o ? qcB  : qcA);
        float axp0 = axpf.x, axp1 = axpf.y;
        float qcr = qcf.x, qci = qcf.y;

        ulonglong2 xcu = sU[bi + 102];
        float2 x0 = upk(xcu.x), x1 = upk(xcu.y);
        float xc_x = x0.x, xc_y = x0.y, xc_z = x1.x, xc_w = x1.y;

        float pc0 = xc_x * xc_x + xc_y * xc_y;
        float pc1 = xc_z * xc_z + xc_w * xc_w;
        axp0 -= wxc * (2.f * pc0 + pc1);
        axp1 -= wxc * (2.f * pc1 + pc0);
        qcr -= wqc * (xc_x * xc_z + xc_y * xc_w);
        qci -= wqc * (xc_y * xc_z - xc_x * xc_w);

        float spm  = C00 * (pc0 + pc1);
        float phi0 = spm + 2.f * axp0;
        float phi1 = spm + 2.f * axp1;

        float ici0r = -(xc_z * qci + xc_w * qcr);
        float ici0i =   xc_z * qcr - xc_w * qci;
        float ici1r =   xc_x * qci - xc_y * qcr;
        float ici1i =   xc_x * qcr + xc_y * qci;

        float Gr[4][4], Gi[4][4];
        const int sw[4] = {0, 2, 1, 3};
#pragma unroll
        for (int m = 0; m < 4; ++m) {
            float2 a, bb;
            a = upk(Ap[m]); bb = upk(Bp[m]);
            Gr[2][m] = a.x - bb.y;  Gi[2][m] = a.y + bb.x;
            a = upk(Ap[4 + m]); bb = upk(Bp[4 + m]);
            Gr[3][m] = a.x - bb.y;  Gi[3][m] = a.y + bb.x;
            a = upk(Am[sw[m]]); bb = upk(Bm[sw[m]]);
            Gr[1][m] = a.x + bb.y;  Gi[1][m] = bb.x - a.y;
            a = upk(Am[4 + sw[m]]); bb = upk(Bm[4 + sw[m]]);
            Gr[0][m] = a.x + bb.y;  Gi[0][m] = bb.x - a.y;
        }

        float fwm0r = 0.f, fwm0i = 0.f, fwm1r = 0.f, fwm1i = 0.f;
        const int soff[4] = {104, 103, 101, 100};
#pragma unroll
        for (int k = 0; k < 4; ++k) {
            ulonglong2 xsu = sU[bi + soff[k]];
            float2 s0f = upk(xsu.x), s1f = upk(xsu.y);
            float xs_x = s0f.x, xs_y = s0f.y, xs_z = s1f.x, xs_w = s1f.y;
            float G00r = Gr[k][0], G00i = Gi[k][0];
            float G01r = Gr[k][1], G01i = Gi[k][1];
            float G10r = Gr[k][2], G10i = Gi[k][2];
            float G11r = Gr[k][3], G11i = Gi[k][3];
            float fA0r = 2.f * G00r + G11r, fA0i = 2.f * G00i + G11i;
            float fA1r = 2.f * G11r + G00r, fA1i = 2.f * G11i + G00i;
            fwm0r += xs_x * fA0r - xs_y * fA0i;
            fwm0i += xs_x * fA0i + xs_y * fA0r;
            fwm0r += xs_z * G01r - xs_w * G01i;
            fwm0i += xs_z * G01i + xs_w * G01r;
            fwm1r += xs_z * fA1r - xs_w * fA1i;
            fwm1i += xs_z * fA1i + xs_w * fA1r;
            fwm1r += xs_x * G10r - xs_y * G10i;
            fwm1i += xs_x * G10i + xs_y * G10r;
        }

        float s0, c0, s1, c1;
        sincosf(phi0, &s0, &c0);
        sincosf(phi1, &s1, &c1);
        float o0r = xc_x * c0 - xc_y * s0 + ici0r + fwm0r;
        float o0i = xc_x * s0 + xc_y * c0 + ici0i + fwm0i;
        float o1r = xc_z * c1 - xc_w * s1 + ici1r + fwm1r;
        float o1i = xc_z * s1 + xc_w * c1 + ici1i + fwm1i;

        float4* outv = (float4*)(out + ((size_t)(b * (size_t)Lout + l)) * 4);
        *outv = make_float4(o0r * rsP, o0i * rsP, o1r * rsP, o1i * rsP);
    }
}

extern "C" void kernel_launch(void* const* d_in, const int* in_sizes, int n_in,
                              void* d_out, int out_size)
{
    const float* x_real    = (const float*)d_in[0];
    const float* x_imag    = (const float*)d_in[1];
    const float* task_info = (const float*)d_in[2];
    const float* C00       = (const float*)d_in[3];
    const float* ixpm_w    = (const float*)d_in[4];
    const float* icixpm_w  = (const float*)d_in[5];
    const float* fwm_wr    = (const float*)d_in[6];
    const float* fwm_wi    = (const float*)d_in[7];

    int B = in_sizes[2] / 4;
    int M = in_sizes[0] / (B * 2);
    int Lout = M - NTAPS + 1;

    // build weight table -> staging buffer -> constant bank (device-addr resolved)
    prep_weights<<<(NT3 + 255) / 256, 256>>>(ixpm_w, icixpm_w, fwm_wr, fwm_wi);
    void* srcAddr = nullptr;
    void* dstAddr = nullptr;
    cudaGetSymbolAddress(&srcAddr, gWstage);
    cudaGetSymbolAddress(&dstAddr, cW);
    cudaMemcpyAsync(dstAddr, srcAddr, NW * sizeof(ull),
                    cudaMemcpyDeviceToDevice, 0);

    cudaFuncSetAttribute(snse_kernel,
                         cudaFuncAttributeMaxDynamicSharedMemorySize, DYNBYTES);

    dim3 grid((Lout + OUTS - 1) / OUTS, B);
    snse_kernel<<<grid, TILE, DYNBYTES>>>(x_real, x_imag, task_info, C00,
                                          ixpm_w, icixpm_w,
                                          (float*)d_out, M, Lout);
}